// round 1
// baseline (speedup 1.0000x reference)
#include <cuda_runtime.h>
#include <math.h>
#include <stdint.h>

#define QLEN 1024
#define BSZ  4
#define EDIM 1024
#define NH   16
#define DH   64
#define SCALE_F 0.125f
#define LN_EPS 1e-5f

#define MB (QLEN * BSZ)           // 4096 rows for token-major matrices
#define HDIM (3 * NH * DH)        // 3072

// ---------------- scratch (device globals: allocation-free) ----------------
__device__ float g_heads_r[(size_t)MB * HDIM];       // 50 MB
__device__ float g_heads_p[(size_t)MB * HDIM];       // 50 MB
__device__ float g_rk[(size_t)QLEN * NH * DH];       // 4 MB
__device__ float g_S[(size_t)64 * QLEN * QLEN];      // 256 MB  (scores -> probs in place)
__device__ float g_vecr[(size_t)MB * EDIM];          // 16 MB
__device__ float g_vecp[(size_t)MB * EDIM];
__device__ float g_yr[(size_t)MB * EDIM];
__device__ float g_yp[(size_t)MB * EDIM];

// ---------------- generic SGEMM: C(M,N) = A(M,K) @ B(N,K)^T [+ R] ----------
// 128x128 block tile, 16-deep K tile, 256 threads, 8x8 microtile.
__global__ void __launch_bounds__(256) sgemm_tn(
    const float* __restrict__ A, const float* __restrict__ B,
    const float* __restrict__ R, float* __restrict__ C,
    int M, int N, int K)
{
    __shared__ __align__(16) float As[16][128];
    __shared__ __align__(16) float Bs[16][128];
    const int tid = threadIdx.x;
    const int tx = tid & 15, ty = tid >> 4;
    const int m0 = blockIdx.y * 128, n0 = blockIdx.x * 128;

    float acc[8][8];
    #pragma unroll
    for (int i = 0; i < 8; i++)
        #pragma unroll
        for (int j = 0; j < 8; j++) acc[i][j] = 0.f;

    for (int k0 = 0; k0 < K; k0 += 16) {
        #pragma unroll
        for (int u = 0; u < 8; u++) {
            int e = tid + u * 256;
            int m = e >> 4, k = e & 15;
            As[k][m] = A[(size_t)(m0 + m) * K + (k0 + k)];
            Bs[k][m] = B[(size_t)(n0 + m) * K + (k0 + k)];
        }
        __syncthreads();
        #pragma unroll
        for (int k = 0; k < 16; k++) {
            float4 a0 = *(const float4*)&As[k][ty * 8];
            float4 a1 = *(const float4*)&As[k][ty * 8 + 4];
            float4 b0 = *(const float4*)&Bs[k][tx * 8];
            float4 b1 = *(const float4*)&Bs[k][tx * 8 + 4];
            float a[8] = {a0.x, a0.y, a0.z, a0.w, a1.x, a1.y, a1.z, a1.w};
            float b[8] = {b0.x, b0.y, b0.z, b0.w, b1.x, b1.y, b1.z, b1.w};
            #pragma unroll
            for (int i = 0; i < 8; i++)
                #pragma unroll
                for (int j = 0; j < 8; j++)
                    acc[i][j] += a[i] * b[j];
        }
        __syncthreads();
    }
    #pragma unroll
    for (int i = 0; i < 8; i++) {
        int m = m0 + ty * 8 + i;
        #pragma unroll
        for (int j = 0; j < 8; j++) {
            int n = n0 + tx * 8 + j;
            float v = acc[i][j];
            if (R) v += R[(size_t)m * N + n];
            C[(size_t)m * N + n] = v;
        }
    }
}

// ---------------- fused score kernel ---------------------------------------
// One CTA per (bn, lower-triangular 64x64 tile). Computes 5 dot products:
//   A1=(qr+rwb)·kr, A2=(qp+rwb)·kp, A3=(qr+rwb)·kp,
//   B1=(qr+rrb)·rk[1023+j-i], B2=(qp+rrb)·rk[1023+j-i]
// score = (sqrt((A1-A2)^2+(2*A3)^2) + sqrt(B1^2+B2^2)) * SCALE, -inf for j>i.
__global__ void __launch_bounds__(256) score_kernel(
    const float* __restrict__ hr, const float* __restrict__ hp,
    const float* __restrict__ rk, const float* __restrict__ rwb,
    const float* __restrict__ rrb, float* __restrict__ S)
{
    extern __shared__ float sm[];
    float* qr_s  = sm;                  // 64 x 65
    float* qp_s  = qr_s + 64 * 65;
    float* kr_s  = qp_s + 64 * 65;
    float* kp_s  = kr_s + 64 * 65;
    float* rk_s  = kp_s + 64 * 65;      // 128 x 65
    float* rwb_s = rk_s + 128 * 65;     // 64
    float* rrb_s = rwb_s + 64;          // 64

    const int bn = blockIdx.y;
    const int b = bn >> 4, n = bn & 15;

    // map linear tile id -> (it, jt) with jt <= it
    int t = blockIdx.x;
    int it = (int)((sqrtf(8.f * t + 1.f) - 1.f) * 0.5f);
    while ((it + 1) * (it + 2) / 2 <= t) it++;
    while (it * (it + 1) / 2 > t) it--;
    const int jt = t - it * (it + 1) / 2;
    const int i0 = it * 64, j0 = jt * 64;

    const int tid = threadIdx.x;
    #pragma unroll
    for (int u = 0; u < 16; u++) {
        int e = tid + u * 256;
        int rr = e >> 6, d = e & 63;
        size_t qoff = (size_t)((i0 + rr) * 4 + b) * HDIM + n * 64 + d;
        qr_s[rr * 65 + d] = hr[qoff];
        qp_s[rr * 65 + d] = hp[qoff];
        size_t koff = (size_t)((j0 + rr) * 4 + b) * HDIM + 1024 + n * 64 + d;
        kr_s[rr * 65 + d] = hr[koff];
        kp_s[rr * 65 + d] = hp[koff];
    }
    const int base = 960 + j0 - i0;   // >= 0 for causal tiles
    #pragma unroll
    for (int u = 0; u < 32; u++) {
        int e = tid + u * 256;
        int L = e >> 6, d = e & 63;
        int krow = base + L;
        krow = krow > 1023 ? 1023 : krow;   // overflow rows are masked anyway
        rk_s[L * 65 + d] = rk[(size_t)krow * (NH * DH) + n * 64 + d];
    }
    if (tid < 64) { rwb_s[tid] = rwb[n * 64 + tid]; rrb_s[tid] = rrb[n * 64 + tid]; }
    __syncthreads();

    const int tx = tid & 15, ty = tid >> 4;
    float a1[4][4] = {}, a2[4][4] = {}, a3[4][4] = {}, c1[4][4] = {}, c2[4][4] = {};
    const int Lb = 60 + 4 * (tx - ty);   // rk_s row for (jj-ii) = -3

    #pragma unroll 4
    for (int d = 0; d < 64; d++) {
        float w  = rwb_s[d];
        float rb = rrb_s[d];
        float qwr[4], qwp[4], qbr[4], qbp[4];
        #pragma unroll
        for (int ii = 0; ii < 4; ii++) {
            float qr = qr_s[(ty * 4 + ii) * 65 + d];
            float qp = qp_s[(ty * 4 + ii) * 65 + d];
            qwr[ii] = qr + w;  qwp[ii] = qp + w;
            qbr[ii] = qr + rb; qbp[ii] = qp + rb;
        }
        float kr[4], kp[4];
        #pragma unroll
        for (int jj = 0; jj < 4; jj++) {
            kr[jj] = kr_s[(tx * 4 + jj) * 65 + d];
            kp[jj] = kp_s[(tx * 4 + jj) * 65 + d];
        }
        float rv[7];
        #pragma unroll
        for (int l = 0; l < 7; l++) rv[l] = rk_s[(Lb + l) * 65 + d];

        #pragma unroll
        for (int ii = 0; ii < 4; ii++)
            #pragma unroll
            for (int jj = 0; jj < 4; jj++) {
                a1[ii][jj] += qwr[ii] * kr[jj];
                a2[ii][jj] += qwp[ii] * kp[jj];
                a3[ii][jj] += qwr[ii] * kp[jj];
                float rvv = rv[jj - ii + 3];
                c1[ii][jj] += qbr[ii] * rvv;
                c2[ii][jj] += qbp[ii] * rvv;
            }
    }

    const size_t Sbase = (size_t)bn * QLEN * QLEN;
    const float NEG_INF = __int_as_float(0xff800000);
    #pragma unroll
    for (int ii = 0; ii < 4; ii++) {
        int i = i0 + ty * 4 + ii;
        #pragma unroll
        for (int jj = 0; jj < 4; jj++) {
            int j = j0 + tx * 4 + jj;
            float acr = a1[ii][jj] - a2[ii][jj];
            float acp = 2.0f * a3[ii][jj];
            float bdr = c1[ii][jj], bdp = c2[ii][jj];
            float s = (sqrtf(acr * acr + acp * acp) + sqrtf(bdr * bdr + bdp * bdp)) * SCALE_F;
            if (j > i) s = NEG_INF;
            S[Sbase + (size_t)i * QLEN + j] = s;
        }
    }
}

// ---------------- masked row softmax (in place), zeros for j>i -------------
__global__ void __launch_bounds__(256) softmax_kernel(float* __restrict__ S)
{
    const int i = blockIdx.x, bn = blockIdx.y;
    float* row = S + (size_t)bn * QLEN * QLEN + (size_t)i * QLEN;
    const int tid = threadIdx.x;
    __shared__ float red[256];

    float m = -1e30f;
    for (int j = tid; j <= i; j += 256) m = fmaxf(m, row[j]);
    red[tid] = m; __syncthreads();
    for (int s = 128; s > 0; s >>= 1) { if (tid < s) red[tid] = fmaxf(red[tid], red[tid + s]); __syncthreads(); }
    m = red[0]; __syncthreads();

    float sum = 0.f;
    for (int j = tid; j <= i; j += 256) { float p = expf(row[j] - m); row[j] = p; sum += p; }
    red[tid] = sum; __syncthreads();
    for (int s = 128; s > 0; s >>= 1) { if (tid < s) red[tid] += red[tid + s]; __syncthreads(); }
    const float inv = 1.f / red[0];
    __syncthreads();

    for (int j = tid; j < QLEN; j += 256) row[j] = (j <= i) ? row[j] * inv : 0.f;
}

// ---------------- P @ V (both streams), causal-trimmed K loop --------------
__global__ void __launch_bounds__(256) pv_kernel(
    const float* __restrict__ P, const float* __restrict__ hr,
    const float* __restrict__ hp, float* __restrict__ vr, float* __restrict__ vp)
{
    __shared__ __align__(16) float Ps[16][128];
    __shared__ __align__(16) float Vs[16][128];
    const int bn = blockIdx.y;
    const int b = bn >> 4, n = bn & 15;
    const int i0 = blockIdx.x * 128;
    const int tid = threadIdx.x, tx = tid & 15, ty = tid >> 4;
    const float* Pb = P + (size_t)bn * QLEN * QLEN;

    float acc[8][8];
    #pragma unroll
    for (int i = 0; i < 8; i++)
        #pragma unroll
        for (int j = 0; j < 8; j++) acc[i][j] = 0.f;

    const int kmax = i0 + 128;   // P is exactly zero for j > i
    for (int k0 = 0; k0 < kmax; k0 += 16) {
        #pragma unroll
        for (int u = 0; u < 8; u++) {
            int e = tid + u * 256;
            int m = e >> 4, k = e & 15;
            Ps[k][m] = Pb[(size_t)(i0 + m) * QLEN + k0 + k];
            int kk = e >> 7, c = e & 127;
            size_t voff = (size_t)((k0 + kk) * 4 + b) * HDIM + 2048 + n * 64;
            Vs[kk][c] = (c < 64) ? hr[voff + c] : hp[voff + (c - 64)];
        }
        __syncthreads();
        #pragma unroll
        for (int k = 0; k < 16; k++) {
            float4 a0 = *(const float4*)&Ps[k][ty * 8];
            float4 a1 = *(const float4*)&Ps[k][ty * 8 + 4];
            float4 b0 = *(const float4*)&Vs[k][tx * 8];
            float4 b1 = *(const float4*)&Vs[k][tx * 8 + 4];
            float a[8] = {a0.x, a0.y, a0.z, a0.w, a1.x, a1.y, a1.z, a1.w};
            float bb[8] = {b0.x, b0.y, b0.z, b0.w, b1.x, b1.y, b1.z, b1.w};
            #pragma unroll
            for (int i = 0; i < 8; i++)
                #pragma unroll
                for (int j = 0; j < 8; j++)
                    acc[i][j] += a[i] * bb[j];
        }
        __syncthreads();
    }
    #pragma unroll
    for (int ii = 0; ii < 8; ii++) {
        int i = i0 + ty * 8 + ii;
        size_t off = (size_t)(i * 4 + b) * EDIM + n * 64;
        #pragma unroll
        for (int jj = 0; jj < 8; jj++) {
            int c = tx * 8 + jj;
            if (c < 64) vr[off + c] = acc[ii][jj];
            else        vp[off + (c - 64)] = acc[ii][jj];
        }
    }
}

// ---------------- LayerNorm over E ----------------------------------------
__global__ void __launch_bounds__(256) ln_kernel(
    const float* __restrict__ Y, const float* __restrict__ g,
    const float* __restrict__ be, float* __restrict__ out)
{
    const int row = blockIdx.x;
    const float* y = Y + (size_t)row * EDIM;
    float* o = out + (size_t)row * EDIM;
    const int tid = threadIdx.x;
    __shared__ float red[256];

    float s = 0.f;
    for (int e = tid; e < EDIM; e += 256) s += y[e];
    red[tid] = s; __syncthreads();
    for (int k = 128; k > 0; k >>= 1) { if (tid < k) red[tid] += red[tid + k]; __syncthreads(); }
    const float mu = red[0] * (1.f / EDIM);
    __syncthreads();

    float sq = 0.f;
    for (int e = tid; e < EDIM; e += 256) { float d = y[e] - mu; sq += d * d; }
    red[tid] = sq; __syncthreads();
    for (int k = 128; k > 0; k >>= 1) { if (tid < k) red[tid] += red[tid + k]; __syncthreads(); }
    const float rstd = rsqrtf(red[0] * (1.f / EDIM) + LN_EPS);

    for (int e = tid; e < EDIM; e += 256)
        o[e] = (y[e] - mu) * rstd * g[e] + be[e];
}

// ---------------- launch ---------------------------------------------------
extern "C" void kernel_launch(void* const* d_in, const int* in_sizes, int n_in,
                              void* d_out, int out_size)
{
    (void)in_sizes; (void)n_in; (void)out_size;
    const float* w_real  = (const float*)d_in[0];
    const float* w_phase = (const float*)d_in[1];
    const float* r       = (const float*)d_in[2];
    const float* r_w_b   = (const float*)d_in[3];
    const float* r_r_b   = (const float*)d_in[4];
    const float* W_qkv   = (const float*)d_in[5];
    const float* W_qkv1  = (const float*)d_in[6];
    const float* W_r     = (const float*)d_in[7];
    const float* W_o     = (const float*)d_in[8];
    const float* W_o1    = (const float*)d_in[9];
    const float* gamma   = (const float*)d_in[10];
    const float* beta    = (const float*)d_in[11];
    // d_in[12] = attn_mask: causal triu(k=1), handled analytically.

    float *heads_r, *heads_p, *rkb, *S, *vecr, *vecp, *yr, *yp;
    cudaGetSymbolAddress((void**)&heads_r, g_heads_r);
    cudaGetSymbolAddress((void**)&heads_p, g_heads_p);
    cudaGetSymbolAddress((void**)&rkb,     g_rk);
    cudaGetSymbolAddress((void**)&S,       g_S);
    cudaGetSymbolAddress((void**)&vecr,    g_vecr);
    cudaGetSymbolAddress((void**)&vecp,    g_vecp);
    cudaGetSymbolAddress((void**)&yr,      g_yr);
    cudaGetSymbolAddress((void**)&yp,      g_yp);

    const dim3 thr(256);

    // projections
    sgemm_tn<<<dim3(HDIM / 128, MB / 128), thr>>>(w_real,  W_qkv,  nullptr, heads_r, MB, HDIM, EDIM);
    sgemm_tn<<<dim3(HDIM / 128, MB / 128), thr>>>(w_phase, W_qkv1, nullptr, heads_p, MB, HDIM, EDIM);
    sgemm_tn<<<dim3(8, 8), thr>>>(r, W_r, nullptr, rkb, QLEN, NH * DH, EDIM);

    // fused scores (lower-triangular tiles only)
    static const int SCORE_SMEM = (4 * 64 * 65 + 128 * 65 + 128) * 4;  // 100352 B
    cudaFuncSetAttribute(score_kernel, cudaFuncAttributeMaxDynamicSharedMemorySize, SCORE_SMEM);
    score_kernel<<<dim3(136, 64), thr, SCORE_SMEM>>>(heads_r, heads_p, rkb, r_w_b, r_r_b, S);

    softmax_kernel<<<dim3(QLEN, 64), thr>>>(S);
    pv_kernel<<<dim3(QLEN / 128, 64), thr>>>(S, heads_r, heads_p, vecr, vecp);

    // output projections with residual, then LN
    sgemm_tn<<<dim3(EDIM / 128, MB / 128), thr>>>(vecr, W_o,  w_real,  yr, MB, EDIM, EDIM);
    sgemm_tn<<<dim3(EDIM / 128, MB / 128), thr>>>(vecp, W_o1, w_phase, yp, MB, EDIM, EDIM);

    float* out = (float*)d_out;
    ln_kernel<<<MB, thr>>>(yr, gamma, beta, out);
    ln_kernel<<<MB, thr>>>(yp, gamma, beta, out + (size_t)MB * EDIM);
}

// round 2
// speedup vs baseline: 2.3067x; 2.3067x over previous
#include <cuda_runtime.h>
#include <math.h>
#include <stdint.h>

#define QLEN 1024
#define BSZ  4
#define EDIM 1024
#define NH   16
#define DH   64
#define SCALE_F 0.125f
#define LN_EPS 1e-5f

#define MB (QLEN * BSZ)           // 4096 rows for token-major matrices
#define HDIM (3 * NH * DH)        // 3072

// ---------------- scratch (device globals: allocation-free) ----------------
__device__ float g_heads_r[(size_t)MB * HDIM];       // 50 MB
__device__ float g_heads_p[(size_t)MB * HDIM];       // 50 MB
__device__ float g_rk[(size_t)QLEN * NH * DH];       // 4 MB
__device__ float g_S[(size_t)64 * QLEN * QLEN];      // 256 MB  (scores -> probs in place)
__device__ float g_vecr[(size_t)MB * EDIM];          // 16 MB
__device__ float g_vecp[(size_t)MB * EDIM];
__device__ float g_yr[(size_t)MB * EDIM];
__device__ float g_yp[(size_t)MB * EDIM];

// ================= TF32 tensor-core GEMM: C(M,N) = A(M,K) @ B(N,K)^T [+R] ==
// CTA tile 128x128, 4 warps (64x64 each), K slab 32, cp.async double buffer.
// smem row layout: [row][36] (32 k-floats + 4 pad) -> conflict-free STS.128
// fills and conflict-free m16n8k8 fragment LDS.
#define SLAB_ROW 36
#define SLAB_FLOATS (128 * SLAB_ROW)           // one matrix, one stage
#define GEMM_SMEM_BYTES (4 * SLAB_FLOATS * 4)  // A/B x 2 stages = 73728 B

__device__ __forceinline__ void cp_async16(uint32_t dst, const void* src) {
    asm volatile("cp.async.ca.shared.global [%0], [%1], 16;\n" :: "r"(dst), "l"(src));
}

__global__ void __launch_bounds__(128) tf32_gemm_tn(
    const float* __restrict__ A, const float* __restrict__ B,
    const float* __restrict__ R, float* __restrict__ C,
    int M, int N, int K)
{
    extern __shared__ float sm[];
    const uint32_t sbase = (uint32_t)__cvta_generic_to_shared(sm);
    const int tid = threadIdx.x;
    const int lane = tid & 31, warp = tid >> 5;
    const int g = lane >> 2, tg = lane & 3;        // quad layout
    const int wm = warp >> 1, wn = warp & 1;       // warp grid 2x2
    const int m0 = blockIdx.y * 128, n0 = blockIdx.x * 128;

    // stage offsets in floats: [A0, B0, A1, B1]
    const int stA[2] = {0, 2 * SLAB_FLOATS};
    const int stB[2] = {SLAB_FLOATS, 3 * SLAB_FLOATS};

    float c[4][8][4];
    #pragma unroll
    for (int mi = 0; mi < 4; mi++)
        #pragma unroll
        for (int ni = 0; ni < 8; ni++)
            #pragma unroll
            for (int q = 0; q < 4; q++) c[mi][ni][q] = 0.f;

    const int NS = K / 32;

    // slab loader: 128 rows x 32 floats for A and B each (8 float4 per thread each)
    auto load_slab = [&](int s, int st) {
        const int k0 = s * 32;
        #pragma unroll
        for (int u = 0; u < 8; u++) {
            int e = tid + u * 128;
            int m = e >> 3, kg = e & 7;
            uint32_t da = sbase + (uint32_t)(stA[st] + m * SLAB_ROW + kg * 4) * 4u;
            cp_async16(da, A + (size_t)(m0 + m) * K + k0 + kg * 4);
            uint32_t db = sbase + (uint32_t)(stB[st] + m * SLAB_ROW + kg * 4) * 4u;
            cp_async16(db, B + (size_t)(n0 + m) * K + k0 + kg * 4);
        }
        asm volatile("cp.async.commit_group;\n");
    };

    load_slab(0, 0);

    for (int s = 0; s < NS; s++) {
        const int st = s & 1;
        if (s + 1 < NS) {
            load_slab(s + 1, st ^ 1);
            asm volatile("cp.async.wait_group 1;\n");
        } else {
            asm volatile("cp.async.wait_group 0;\n");
        }
        __syncthreads();

        const float* As = sm + stA[st];
        const float* Bs = sm + stB[st];
        #pragma unroll
        for (int kk = 0; kk < 4; kk++) {
            uint32_t a[4][4], b[8][2];
            #pragma unroll
            for (int mi = 0; mi < 4; mi++) {
                int base = (wm * 64 + mi * 16 + g) * SLAB_ROW + kk * 8 + tg;
                a[mi][0] = __float_as_uint(As[base]);
                a[mi][1] = __float_as_uint(As[base + 8 * SLAB_ROW]);
                a[mi][2] = __float_as_uint(As[base + 4]);
                a[mi][3] = __float_as_uint(As[base + 8 * SLAB_ROW + 4]);
            }
            #pragma unroll
            for (int ni = 0; ni < 8; ni++) {
                int base = (wn * 64 + ni * 8 + g) * SLAB_ROW + kk * 8 + tg;
                b[ni][0] = __float_as_uint(Bs[base]);
                b[ni][1] = __float_as_uint(Bs[base + 4]);
            }
            #pragma unroll
            for (int mi = 0; mi < 4; mi++)
                #pragma unroll
                for (int ni = 0; ni < 8; ni++)
                    asm volatile(
                        "mma.sync.aligned.m16n8k8.row.col.f32.tf32.tf32.f32 "
                        "{%0,%1,%2,%3}, {%4,%5,%6,%7}, {%8,%9}, {%0,%1,%2,%3};\n"
                        : "+f"(c[mi][ni][0]), "+f"(c[mi][ni][1]),
                          "+f"(c[mi][ni][2]), "+f"(c[mi][ni][3])
                        : "r"(a[mi][0]), "r"(a[mi][1]), "r"(a[mi][2]), "r"(a[mi][3]),
                          "r"(b[ni][0]), "r"(b[ni][1]));
        }
        __syncthreads();
    }

    // epilogue: C[g][2tg], C[g][2tg+1], C[g+8][2tg], C[g+8][2tg+1] per mma tile
    #pragma unroll
    for (int mi = 0; mi < 4; mi++) {
        int r0 = m0 + wm * 64 + mi * 16 + g;
        #pragma unroll
        for (int ni = 0; ni < 8; ni++) {
            int cc = n0 + wn * 64 + ni * 8 + 2 * tg;
            float2 v0 = make_float2(c[mi][ni][0], c[mi][ni][1]);
            float2 v1 = make_float2(c[mi][ni][2], c[mi][ni][3]);
            if (R) {
                float2 u0 = *(const float2*)&R[(size_t)r0 * N + cc];
                float2 u1 = *(const float2*)&R[(size_t)(r0 + 8) * N + cc];
                v0.x += u0.x; v0.y += u0.y; v1.x += u1.x; v1.y += u1.y;
            }
            *(float2*)&C[(size_t)r0 * N + cc] = v0;
            *(float2*)&C[(size_t)(r0 + 8) * N + cc] = v1;
        }
    }
}

// ---------------- fused score kernel ---------------------------------------
__global__ void __launch_bounds__(256) score_kernel(
    const float* __restrict__ hr, const float* __restrict__ hp,
    const float* __restrict__ rk, const float* __restrict__ rwb,
    const float* __restrict__ rrb, float* __restrict__ S)
{
    extern __shared__ float smf[];
    float* qr_s  = smf;                 // 64 x 65
    float* qp_s  = qr_s + 64 * 65;
    float* kr_s  = qp_s + 64 * 65;
    float* kp_s  = kr_s + 64 * 65;
    float* rk_s  = kp_s + 64 * 65;      // 128 x 65
    float* rwb_s = rk_s + 128 * 65;     // 64
    float* rrb_s = rwb_s + 64;          // 64

    const int bn = blockIdx.y;
    const int b = bn >> 4, n = bn & 15;

    int t = blockIdx.x;
    int it = (int)((sqrtf(8.f * t + 1.f) - 1.f) * 0.5f);
    while ((it + 1) * (it + 2) / 2 <= t) it++;
    while (it * (it + 1) / 2 > t) it--;
    const int jt = t - it * (it + 1) / 2;
    const int i0 = it * 64, j0 = jt * 64;

    const int tid = threadIdx.x;
    #pragma unroll
    for (int u = 0; u < 16; u++) {
        int e = tid + u * 256;
        int rr = e >> 6, d = e & 63;
        size_t qoff = (size_t)((i0 + rr) * 4 + b) * HDIM + n * 64 + d;
        qr_s[rr * 65 + d] = hr[qoff];
        qp_s[rr * 65 + d] = hp[qoff];
        size_t koff = (size_t)((j0 + rr) * 4 + b) * HDIM + 1024 + n * 64 + d;
        kr_s[rr * 65 + d] = hr[koff];
        kp_s[rr * 65 + d] = hp[koff];
    }
    const int base = 960 + j0 - i0;
    #pragma unroll
    for (int u = 0; u < 32; u++) {
        int e = tid + u * 256;
        int L = e >> 6, d = e & 63;
        int krow = base + L;
        krow = krow > 1023 ? 1023 : krow;
        rk_s[L * 65 + d] = rk[(size_t)krow * (NH * DH) + n * 64 + d];
    }
    if (tid < 64) { rwb_s[tid] = rwb[n * 64 + tid]; rrb_s[tid] = rrb[n * 64 + tid]; }
    __syncthreads();

    const int tx = tid & 15, ty = tid >> 4;
    float a1[4][4] = {}, a2[4][4] = {}, a3[4][4] = {}, c1[4][4] = {}, c2[4][4] = {};
    const int Lb = 60 + 4 * (tx - ty);

    #pragma unroll 4
    for (int d = 0; d < 64; d++) {
        float w  = rwb_s[d];
        float rb = rrb_s[d];
        float qwr[4], qwp[4], qbr[4], qbp[4];
        #pragma unroll
        for (int ii = 0; ii < 4; ii++) {
            float qr = qr_s[(ty * 4 + ii) * 65 + d];
            float qp = qp_s[(ty * 4 + ii) * 65 + d];
            qwr[ii] = qr + w;  qwp[ii] = qp + w;
            qbr[ii] = qr + rb; qbp[ii] = qp + rb;
        }
        float kr[4], kp[4];
        #pragma unroll
        for (int jj = 0; jj < 4; jj++) {
            kr[jj] = kr_s[(tx * 4 + jj) * 65 + d];
            kp[jj] = kp_s[(tx * 4 + jj) * 65 + d];
        }
        float rv[7];
        #pragma unroll
        for (int l = 0; l < 7; l++) rv[l] = rk_s[(Lb + l) * 65 + d];

        #pragma unroll
        for (int ii = 0; ii < 4; ii++)
            #pragma unroll
            for (int jj = 0; jj < 4; jj++) {
                a1[ii][jj] += qwr[ii] * kr[jj];
                a2[ii][jj] += qwp[ii] * kp[jj];
                a3[ii][jj] += qwr[ii] * kp[jj];
                float rvv = rv[jj - ii + 3];
                c1[ii][jj] += qbr[ii] * rvv;
                c2[ii][jj] += qbp[ii] * rvv;
            }
    }

    const size_t Sbase = (size_t)bn * QLEN * QLEN;
    const float NEG_INF = __int_as_float(0xff800000);
    #pragma unroll
    for (int ii = 0; ii < 4; ii++) {
        int i = i0 + ty * 4 + ii;
        #pragma unroll
        for (int jj = 0; jj < 4; jj++) {
            int j = j0 + tx * 4 + jj;
            float acr = a1[ii][jj] - a2[ii][jj];
            float acp = 2.0f * a3[ii][jj];
            float bdr = c1[ii][jj], bdp = c2[ii][jj];
            float s = (sqrtf(acr * acr + acp * acp) + sqrtf(bdr * bdr + bdp * bdp)) * SCALE_F;
            if (j > i) s = NEG_INF;
            S[Sbase + (size_t)i * QLEN + j] = s;
        }
    }
}

// ---------------- masked row softmax (in place), zeros for j>i -------------
__global__ void __launch_bounds__(256) softmax_kernel(float* __restrict__ S)
{
    const int i = blockIdx.x, bn = blockIdx.y;
    float* row = S + (size_t)bn * QLEN * QLEN + (size_t)i * QLEN;
    const int tid = threadIdx.x;
    __shared__ float red[256];

    float m = -1e30f;
    for (int j = tid; j <= i; j += 256) m = fmaxf(m, row[j]);
    red[tid] = m; __syncthreads();
    for (int s = 128; s > 0; s >>= 1) { if (tid < s) red[tid] = fmaxf(red[tid], red[tid + s]); __syncthreads(); }
    m = red[0]; __syncthreads();

    float sum = 0.f;
    for (int j = tid; j <= i; j += 256) { float p = expf(row[j] - m); row[j] = p; sum += p; }
    red[tid] = sum; __syncthreads();
    for (int s = 128; s > 0; s >>= 1) { if (tid < s) red[tid] += red[tid + s]; __syncthreads(); }
    const float inv = 1.f / red[0];
    __syncthreads();

    for (int j = tid; j < QLEN; j += 256) row[j] = (j <= i) ? row[j] * inv : 0.f;
}

// ---------------- P @ V (both streams), causal-trimmed K loop --------------
__global__ void __launch_bounds__(256) pv_kernel(
    const float* __restrict__ P, const float* __restrict__ hr,
    const float* __restrict__ hp, float* __restrict__ vr, float* __restrict__ vp)
{
    __shared__ __align__(16) float Ps[16][128];
    __shared__ __align__(16) float Vs[16][128];
    const int bn = blockIdx.y;
    const int b = bn >> 4, n = bn & 15;
    const int i0 = blockIdx.x * 128;
    const int tid = threadIdx.x, tx = tid & 15, ty = tid >> 4;
    const float* Pb = P + (size_t)bn * QLEN * QLEN;

    float acc[8][8];
    #pragma unroll
    for (int i = 0; i < 8; i++)
        #pragma unroll
        for (int j = 0; j < 8; j++) acc[i][j] = 0.f;

    const int kmax = i0 + 128;
    for (int k0 = 0; k0 < kmax; k0 += 16) {
        #pragma unroll
        for (int u = 0; u < 8; u++) {
            int e = tid + u * 256;
            int m = e >> 4, k = e & 15;
            Ps[k][m] = Pb[(size_t)(i0 + m) * QLEN + k0 + k];
            int kk = e >> 7, cidx = e & 127;
            size_t voff = (size_t)((k0 + kk) * 4 + b) * HDIM + 2048 + n * 64;
            Vs[kk][cidx] = (cidx < 64) ? hr[voff + cidx] : hp[voff + (cidx - 64)];
        }
        __syncthreads();
        #pragma unroll
        for (int k = 0; k < 16; k++) {
            float4 a0 = *(const float4*)&Ps[k][ty * 8];
            float4 a1 = *(const float4*)&Ps[k][ty * 8 + 4];
            float4 b0 = *(const float4*)&Vs[k][tx * 8];
            float4 b1 = *(const float4*)&Vs[k][tx * 8 + 4];
            float a[8] = {a0.x, a0.y, a0.z, a0.w, a1.x, a1.y, a1.z, a1.w};
            float bb[8] = {b0.x, b0.y, b0.z, b0.w, b1.x, b1.y, b1.z, b1.w};
            #pragma unroll
            for (int i = 0; i < 8; i++)
                #pragma unroll
                for (int j = 0; j < 8; j++)
                    acc[i][j] += a[i] * bb[j];
        }
        __syncthreads();
    }
    #pragma unroll
    for (int ii = 0; ii < 8; ii++) {
        int i = i0 + ty * 8 + ii;
        size_t off = (size_t)(i * 4 + b) * EDIM + n * 64;
        #pragma unroll
        for (int jj = 0; jj < 8; jj++) {
            int cidx = tx * 8 + jj;
            if (cidx < 64) vr[off + cidx] = acc[ii][jj];
            else           vp[off + (cidx - 64)] = acc[ii][jj];
        }
    }
}

// ---------------- LayerNorm over E ----------------------------------------
__global__ void __launch_bounds__(256) ln_kernel(
    const float* __restrict__ Y, const float* __restrict__ g,
    const float* __restrict__ be, float* __restrict__ out)
{
    const int row = blockIdx.x;
    const float* y = Y + (size_t)row * EDIM;
    float* o = out + (size_t)row * EDIM;
    const int tid = threadIdx.x;
    __shared__ float red[256];

    float s = 0.f;
    for (int e = tid; e < EDIM; e += 256) s += y[e];
    red[tid] = s; __syncthreads();
    for (int k = 128; k > 0; k >>= 1) { if (tid < k) red[tid] += red[tid + k]; __syncthreads(); }
    const float mu = red[0] * (1.f / EDIM);
    __syncthreads();

    float sq = 0.f;
    for (int e = tid; e < EDIM; e += 256) { float d = y[e] - mu; sq += d * d; }
    red[tid] = sq; __syncthreads();
    for (int k = 128; k > 0; k >>= 1) { if (tid < k) red[tid] += red[tid + k]; __syncthreads(); }
    const float rstd = rsqrtf(red[0] * (1.f / EDIM) + LN_EPS);

    for (int e = tid; e < EDIM; e += 256)
        o[e] = (y[e] - mu) * rstd * g[e] + be[e];
}

// ---------------- launch ---------------------------------------------------
extern "C" void kernel_launch(void* const* d_in, const int* in_sizes, int n_in,
                              void* d_out, int out_size)
{
    (void)in_sizes; (void)n_in; (void)out_size;
    const float* w_real  = (const float*)d_in[0];
    const float* w_phase = (const float*)d_in[1];
    const float* r       = (const float*)d_in[2];
    const float* r_w_b   = (const float*)d_in[3];
    const float* r_r_b   = (const float*)d_in[4];
    const float* W_qkv   = (const float*)d_in[5];
    const float* W_qkv1  = (const float*)d_in[6];
    const float* W_r     = (const float*)d_in[7];
    const float* W_o     = (const float*)d_in[8];
    const float* W_o1    = (const float*)d_in[9];
    const float* gamma   = (const float*)d_in[10];
    const float* beta    = (const float*)d_in[11];

    float *heads_r, *heads_p, *rkb, *S, *vecr, *vecp, *yr, *yp;
    cudaGetSymbolAddress((void**)&heads_r, g_heads_r);
    cudaGetSymbolAddress((void**)&heads_p, g_heads_p);
    cudaGetSymbolAddress((void**)&rkb,     g_rk);
    cudaGetSymbolAddress((void**)&S,       g_S);
    cudaGetSymbolAddress((void**)&vecr,    g_vecr);
    cudaGetSymbolAddress((void**)&vecp,    g_vecp);
    cudaGetSymbolAddress((void**)&yr,      g_yr);
    cudaGetSymbolAddress((void**)&yp,      g_yp);

    cudaFuncSetAttribute(tf32_gemm_tn, cudaFuncAttributeMaxDynamicSharedMemorySize, GEMM_SMEM_BYTES);

    // projections (tensor cores, tf32)
    tf32_gemm_tn<<<dim3(HDIM / 128, MB / 128), 128, GEMM_SMEM_BYTES>>>(w_real,  W_qkv,  nullptr, heads_r, MB, HDIM, EDIM);
    tf32_gemm_tn<<<dim3(HDIM / 128, MB / 128), 128, GEMM_SMEM_BYTES>>>(w_phase, W_qkv1, nullptr, heads_p, MB, HDIM, EDIM);
    tf32_gemm_tn<<<dim3(8, 8), 128, GEMM_SMEM_BYTES>>>(r, W_r, nullptr, rkb, QLEN, NH * DH, EDIM);

    // fused scores (lower-triangular tiles only)
    static const int SCORE_SMEM = (4 * 64 * 65 + 128 * 65 + 128) * 4;  // 100352 B
    cudaFuncSetAttribute(score_kernel, cudaFuncAttributeMaxDynamicSharedMemorySize, SCORE_SMEM);
    score_kernel<<<dim3(136, 64), 256, SCORE_SMEM>>>(heads_r, heads_p, rkb, r_w_b, r_r_b, S);

    softmax_kernel<<<dim3(QLEN, 64), 256>>>(S);
    pv_kernel<<<dim3(QLEN / 128, 64), 256>>>(S, heads_r, heads_p, vecr, vecp);

    // output projections with residual (tensor cores), then LN
    tf32_gemm_tn<<<dim3(EDIM / 128, MB / 128), 128, GEMM_SMEM_BYTES>>>(vecr, W_o,  w_real,  yr, MB, EDIM, EDIM);
    tf32_gemm_tn<<<dim3(EDIM / 128, MB / 128), 128, GEMM_SMEM_BYTES>>>(vecp, W_o1, w_phase, yp, MB, EDIM, EDIM);

    float* out = (float*)d_out;
    ln_kernel<<<MB, 256>>>(yr, gamma, beta, out);
    ln_kernel<<<MB, 256>>>(yp, gamma, beta, out + (size_t)MB * EDIM);
}

// round 3
// speedup vs baseline: 3.5791x; 1.5516x over previous
#include <cuda_runtime.h>
#include <math.h>
#include <stdint.h>

#define QLEN 1024
#define BSZ  4
#define EDIM 1024
#define NH   16
#define DH   64
#define SCALE_F 0.125f
#define LN_EPS 1e-5f

#define MB (QLEN * BSZ)           // 4096 rows for token-major matrices
#define HDIM (3 * NH * DH)        // 3072

// ---------------- scratch (device globals: allocation-free) ----------------
__device__ float g_heads_r[(size_t)MB * HDIM];
__device__ float g_heads_p[(size_t)MB * HDIM];
__device__ float g_rk[(size_t)QLEN * NH * DH];
__device__ float g_S[(size_t)64 * QLEN * QLEN];
__device__ float g_vecr[(size_t)MB * EDIM];
__device__ float g_vecp[(size_t)MB * EDIM];
__device__ float g_yr[(size_t)MB * EDIM];
__device__ float g_yp[(size_t)MB * EDIM];

__device__ __forceinline__ void cp_async16(uint32_t dst, const void* src) {
    asm volatile("cp.async.ca.shared.global [%0], [%1], 16;\n" :: "r"(dst), "l"(src));
}
__device__ __forceinline__ void mma_tf32(
    float& c0, float& c1, float& c2, float& c3,
    uint32_t a0, uint32_t a1, uint32_t a2, uint32_t a3,
    uint32_t b0, uint32_t b1)
{
    asm volatile(
        "mma.sync.aligned.m16n8k8.row.col.f32.tf32.tf32.f32 "
        "{%0,%1,%2,%3}, {%4,%5,%6,%7}, {%8,%9}, {%0,%1,%2,%3};\n"
        : "+f"(c0), "+f"(c1), "+f"(c2), "+f"(c3)
        : "r"(a0), "r"(a1), "r"(a2), "r"(a3), "r"(b0), "r"(b1));
}

// ================= TF32 tensor-core GEMM: C(M,N) = A(M,K) @ B(N,K)^T [+R] ==
#define SLAB_ROW 36
#define SLAB_FLOATS (128 * SLAB_ROW)
#define GEMM_SMEM_BYTES (4 * SLAB_FLOATS * 4)

__global__ void __launch_bounds__(128) tf32_gemm_tn(
    const float* __restrict__ A, const float* __restrict__ B,
    const float* __restrict__ R, float* __restrict__ C,
    int M, int N, int K)
{
    extern __shared__ float sm[];
    const uint32_t sbase = (uint32_t)__cvta_generic_to_shared(sm);
    const int tid = threadIdx.x;
    const int lane = tid & 31, warp = tid >> 5;
    const int g = lane >> 2, tg = lane & 3;
    const int wm = warp >> 1, wn = warp & 1;
    const int m0 = blockIdx.y * 128, n0 = blockIdx.x * 128;

    const int stA[2] = {0, 2 * SLAB_FLOATS};
    const int stB[2] = {SLAB_FLOATS, 3 * SLAB_FLOATS};

    float c[4][8][4];
    #pragma unroll
    for (int mi = 0; mi < 4; mi++)
        #pragma unroll
        for (int ni = 0; ni < 8; ni++)
            #pragma unroll
            for (int q = 0; q < 4; q++) c[mi][ni][q] = 0.f;

    const int NS = K / 32;
    auto load_slab = [&](int s, int st) {
        const int k0 = s * 32;
        #pragma unroll
        for (int u = 0; u < 8; u++) {
            int e = tid + u * 128;
            int m = e >> 3, kg = e & 7;
            cp_async16(sbase + (uint32_t)(stA[st] + m * SLAB_ROW + kg * 4) * 4u,
                       A + (size_t)(m0 + m) * K + k0 + kg * 4);
            cp_async16(sbase + (uint32_t)(stB[st] + m * SLAB_ROW + kg * 4) * 4u,
                       B + (size_t)(n0 + m) * K + k0 + kg * 4);
        }
        asm volatile("cp.async.commit_group;\n");
    };

    load_slab(0, 0);
    for (int s = 0; s < NS; s++) {
        const int st = s & 1;
        if (s + 1 < NS) { load_slab(s + 1, st ^ 1); asm volatile("cp.async.wait_group 1;\n"); }
        else            { asm volatile("cp.async.wait_group 0;\n"); }
        __syncthreads();

        const float* As = sm + stA[st];
        const float* Bs = sm + stB[st];
        #pragma unroll
        for (int kk = 0; kk < 4; kk++) {
            uint32_t a[4][4], b[8][2];
            #pragma unroll
            for (int mi = 0; mi < 4; mi++) {
                int base = (wm * 64 + mi * 16 + g) * SLAB_ROW + kk * 8 + tg;
                a[mi][0] = __float_as_uint(As[base]);
                a[mi][1] = __float_as_uint(As[base + 8 * SLAB_ROW]);
                a[mi][2] = __float_as_uint(As[base + 4]);
                a[mi][3] = __float_as_uint(As[base + 8 * SLAB_ROW + 4]);
            }
            #pragma unroll
            for (int ni = 0; ni < 8; ni++) {
                int base = (wn * 64 + ni * 8 + g) * SLAB_ROW + kk * 8 + tg;
                b[ni][0] = __float_as_uint(Bs[base]);
                b[ni][1] = __float_as_uint(Bs[base + 4]);
            }
            #pragma unroll
            for (int mi = 0; mi < 4; mi++)
                #pragma unroll
                for (int ni = 0; ni < 8; ni++)
                    mma_tf32(c[mi][ni][0], c[mi][ni][1], c[mi][ni][2], c[mi][ni][3],
                             a[mi][0], a[mi][1], a[mi][2], a[mi][3],
                             b[ni][0], b[ni][1]);
        }
        __syncthreads();
    }

    #pragma unroll
    for (int mi = 0; mi < 4; mi++) {
        int r0 = m0 + wm * 64 + mi * 16 + g;
        #pragma unroll
        for (int ni = 0; ni < 8; ni++) {
            int cc = n0 + wn * 64 + ni * 8 + 2 * tg;
            float2 v0 = make_float2(c[mi][ni][0], c[mi][ni][1]);
            float2 v1 = make_float2(c[mi][ni][2], c[mi][ni][3]);
            if (R) {
                float2 u0 = *(const float2*)&R[(size_t)r0 * N + cc];
                float2 u1 = *(const float2*)&R[(size_t)(r0 + 8) * N + cc];
                v0.x += u0.x; v0.y += u0.y; v1.x += u1.x; v1.y += u1.y;
            }
            *(float2*)&C[(size_t)r0 * N + cc] = v0;
            *(float2*)&C[(size_t)(r0 + 8) * N + cc] = v1;
        }
    }
}

// ================= fused score kernel (tensor cores) =======================
// Per CTA: one 64x64 lower-triangular tile for one (b, n).
// 5 shared-operand tf32 mma products + per-column bias vectors:
//   A1 = qr.kr + (rwb.kr)[j]   A2 = qp.kp + (rwb.kp)[j]   A3 = qr.kp + (rwb.kp)[j]
//   B1 = qr.rk + (rrb.rk)[L]   B2 = qp.rk + (rrb.rk)[L],  L = j - i + 63
// smem layout (floats), pad 68 per row:
//   qr[64*68] qp[64*68] kr[64*68] kp[64*68] rk[128*68]
//   wkr[64] wkp[64] brk[128] rwb[64] rrb[64]
// E_r/E_p (64x132 each) alias over kr/kp/rk after the mma pass.
#define SK_QR   0
#define SK_QP   (64 * 68)
#define SK_KR   (2 * 64 * 68)
#define SK_KP   (3 * 64 * 68)
#define SK_RK   (4 * 64 * 68)
#define SK_BIAS (4 * 64 * 68 + 128 * 68)        // 26112
#define SK_WKR  (SK_BIAS)
#define SK_WKP  (SK_BIAS + 64)
#define SK_BRK  (SK_BIAS + 128)
#define SK_RWB  (SK_BIAS + 256)
#define SK_RRB  (SK_BIAS + 320)
#define SK_FLOATS (SK_BIAS + 384)               // 26496
#define SK_SMEM_BYTES (SK_FLOATS * 4)           // 105984
#define SK_ER   SK_KR                            // 64*132 = 8448 floats
#define SK_EP   (SK_KR + 8448)

__global__ void __launch_bounds__(256) score_kernel(
    const float* __restrict__ hr, const float* __restrict__ hp,
    const float* __restrict__ rk, const float* __restrict__ rwb,
    const float* __restrict__ rrb, float* __restrict__ S)
{
    extern __shared__ float sm[];
    const int bn = blockIdx.y;
    const int b = bn >> 4, n = bn & 15;

    int t = blockIdx.x;
    int it = (int)((sqrtf(8.f * t + 1.f) - 1.f) * 0.5f);
    while ((it + 1) * (it + 2) / 2 <= t) it++;
    while (it * (it + 1) / 2 > t) it--;
    const int jt = t - it * (it + 1) / 2;
    const int i0 = it * 64, j0 = jt * 64;
    const bool diag = (it == jt);

    const int tid = threadIdx.x;

    // ---- load operands (float4) ----
    #pragma unroll
    for (int u = 0; u < 4; u++) {
        int e = tid + u * 256;
        int row = e >> 4, f4 = (e & 15) * 4;
        size_t qoff = (size_t)((i0 + row) * 4 + b) * HDIM + n * 64 + f4;
        *(float4*)&sm[SK_QR + row * 68 + f4] = *(const float4*)&hr[qoff];
        *(float4*)&sm[SK_QP + row * 68 + f4] = *(const float4*)&hp[qoff];
        size_t koff = (size_t)((j0 + row) * 4 + b) * HDIM + 1024 + n * 64 + f4;
        *(float4*)&sm[SK_KR + row * 68 + f4] = *(const float4*)&hr[koff];
        *(float4*)&sm[SK_KP + row * 68 + f4] = *(const float4*)&hp[koff];
    }
    const int base = 960 + j0 - i0;   // >= 0 for causal tiles
    #pragma unroll
    for (int u = 0; u < 8; u++) {
        int e = tid + u * 256;
        int row = e >> 4, f4 = (e & 15) * 4;
        int krow = base + row; krow = krow > 1023 ? 1023 : krow;
        *(float4*)&sm[SK_RK + row * 68 + f4] =
            *(const float4*)&rk[(size_t)krow * (NH * DH) + n * 64 + f4];
    }
    if (tid < 64)  sm[SK_RWB + tid] = rwb[n * 64 + tid];
    else if (tid < 128) sm[SK_RRB + (tid - 64)] = rrb[n * 64 + (tid - 64)];
    __syncthreads();

    // ---- per-column bias vectors ----
    if (tid < 64) {
        float s = 0.f;
        #pragma unroll 8
        for (int d = 0; d < 64; d++) s += sm[SK_RWB + d] * sm[SK_KR + tid * 68 + d];
        sm[SK_WKR + tid] = s;
    } else if (tid < 128) {
        int j = tid - 64; float s = 0.f;
        #pragma unroll 8
        for (int d = 0; d < 64; d++) s += sm[SK_RWB + d] * sm[SK_KP + j * 68 + d];
        sm[SK_WKP + j] = s;
    } else {
        int L = tid - 128; float s = 0.f;
        #pragma unroll 8
        for (int d = 0; d < 64; d++) s += sm[SK_RRB + d] * sm[SK_RK + L * 68 + d];
        sm[SK_BRK + L] = s;
    }
    __syncthreads();

    // ---- mma pass: 5 products ----
    const int lane = tid & 31, warp = tid >> 5;
    const int g = lane >> 2, tg = lane & 3;
    const int wm = warp >> 1, wn = warp & 1;   // rows 16*wm, AC cols 32*wn, BD cols 64*wn

    float A1[4][4] = {}, A2[4][4] = {}, A3[4][4] = {};
    float B1[8][4] = {}, B2[8][4] = {};

    #pragma unroll
    for (int kk = 0; kk < 8; kk++) {
        int arow = (16 * wm + g) * 68 + kk * 8 + tg;
        uint32_t aqr0 = __float_as_uint(sm[SK_QR + arow]);
        uint32_t aqr1 = __float_as_uint(sm[SK_QR + arow + 8 * 68]);
        uint32_t aqr2 = __float_as_uint(sm[SK_QR + arow + 4]);
        uint32_t aqr3 = __float_as_uint(sm[SK_QR + arow + 8 * 68 + 4]);
        uint32_t aqp0 = __float_as_uint(sm[SK_QP + arow]);
        uint32_t aqp1 = __float_as_uint(sm[SK_QP + arow + 8 * 68]);
        uint32_t aqp2 = __float_as_uint(sm[SK_QP + arow + 4]);
        uint32_t aqp3 = __float_as_uint(sm[SK_QP + arow + 8 * 68 + 4]);

        #pragma unroll
        for (int ni = 0; ni < 4; ni++) {
            int brow = (32 * wn + 8 * ni + g) * 68 + kk * 8 + tg;
            uint32_t bkr0 = __float_as_uint(sm[SK_KR + brow]);
            uint32_t bkr1 = __float_as_uint(sm[SK_KR + brow + 4]);
            uint32_t bkp0 = __float_as_uint(sm[SK_KP + brow]);
            uint32_t bkp1 = __float_as_uint(sm[SK_KP + brow + 4]);
            mma_tf32(A1[ni][0], A1[ni][1], A1[ni][2], A1[ni][3],
                     aqr0, aqr1, aqr2, aqr3, bkr0, bkr1);
            mma_tf32(A2[ni][0], A2[ni][1], A2[ni][2], A2[ni][3],
                     aqp0, aqp1, aqp2, aqp3, bkp0, bkp1);
            mma_tf32(A3[ni][0], A3[ni][1], A3[ni][2], A3[ni][3],
                     aqr0, aqr1, aqr2, aqr3, bkp0, bkp1);
        }
        #pragma unroll
        for (int li = 0; li < 8; li++) {
            int rrow = (64 * wn + 8 * li + g) * 68 + kk * 8 + tg;
            uint32_t br0 = __float_as_uint(sm[SK_RK + rrow]);
            uint32_t br1 = __float_as_uint(sm[SK_RK + rrow + 4]);
            mma_tf32(B1[li][0], B1[li][1], B1[li][2], B1[li][3],
                     aqr0, aqr1, aqr2, aqr3, br0, br1);
            mma_tf32(B2[li][0], B2[li][1], B2[li][2], B2[li][3],
                     aqp0, aqp1, aqp2, aqp3, br0, br1);
        }
    }

    // ---- stage E through smem (aliases kr/kp/rk) ----
    __syncthreads();
    #pragma unroll
    for (int li = 0; li < 8; li++) {
        #pragma unroll
        for (int q = 0; q < 4; q++) {
            int row = 16 * wm + g + 8 * (q >> 1);
            int col = 64 * wn + 8 * li + 2 * tg + (q & 1);
            sm[SK_ER + row * 132 + col] = B1[li][q];
            sm[SK_EP + row * 132 + col] = B2[li][q];
        }
    }
    __syncthreads();

    // ---- combine + write ----
    const size_t Sbase = (size_t)bn * QLEN * QLEN;
    #pragma unroll
    for (int ni = 0; ni < 4; ni++) {
        #pragma unroll
        for (int q = 0; q < 4; q++) {
            int row = 16 * wm + g + 8 * (q >> 1);
            int col = 32 * wn + 8 * ni + 2 * tg + (q & 1);
            if (diag && col > row) continue;
            float wkp_c = sm[SK_WKP + col];
            float acr = A1[ni][q] + sm[SK_WKR + col] - A2[ni][q] - wkp_c;
            float acp = 2.0f * (A3[ni][q] + wkp_c);
            int L = col - row + 63;
            float bb = sm[SK_BRK + L];
            float b1 = sm[SK_ER + row * 132 + L] + bb;
            float b2 = sm[SK_EP + row * 132 + L] + bb;
            float s = (sqrtf(acr * acr + acp * acp) + sqrtf(b1 * b1 + b2 * b2)) * SCALE_F;
            S[Sbase + (size_t)(i0 + row) * QLEN + (j0 + col)] = s;
        }
    }
}

// ---------------- masked row softmax (in place), zeros for j>i -------------
__global__ void __launch_bounds__(256) softmax_kernel(float* __restrict__ S)
{
    const int i = blockIdx.x, bn = blockIdx.y;
    float* row = S + (size_t)bn * QLEN * QLEN + (size_t)i * QLEN;
    const int tid = threadIdx.x;
    __shared__ float red[256];

    float m = -1e30f;
    for (int j = tid; j <= i; j += 256) m = fmaxf(m, row[j]);
    red[tid] = m; __syncthreads();
    for (int s = 128; s > 0; s >>= 1) { if (tid < s) red[tid] = fmaxf(red[tid], red[tid + s]); __syncthreads(); }
    m = red[0]; __syncthreads();

    float sum = 0.f;
    for (int j = tid; j <= i; j += 256) { float p = expf(row[j] - m); row[j] = p; sum += p; }
    red[tid] = sum; __syncthreads();
    for (int s = 128; s > 0; s >>= 1) { if (tid < s) red[tid] += red[tid + s]; __syncthreads(); }
    const float inv = 1.f / red[0];
    __syncthreads();

    for (int j = tid; j < QLEN; j += 256) row[j] = (j <= i) ? row[j] * inv : 0.f;
}

// ================= P @ V (tensor cores, both streams) ======================
// CTA: 128 q-rows x 128 cols (64 vr + 64 vp) for one (b, n). 8 warps 4x2.
#define PV_PS_ROW 36
#define PV_VS_ROW 136
#define PV_PS_FLOATS (128 * PV_PS_ROW)
#define PV_VS_FLOATS (32 * PV_VS_ROW)
#define PV_SMEM_BYTES ((2 * PV_PS_FLOATS + 2 * PV_VS_FLOATS) * 4)  // 71680

__global__ void __launch_bounds__(256) pv_kernel(
    const float* __restrict__ P, const float* __restrict__ hr,
    const float* __restrict__ hp, float* __restrict__ vr, float* __restrict__ vp)
{
    extern __shared__ float sm[];
    const uint32_t sbase = (uint32_t)__cvta_generic_to_shared(sm);
    const int bn = blockIdx.y;
    const int b = bn >> 4, n = bn & 15;
    const int i0 = blockIdx.x * 128;
    const int tid = threadIdx.x;
    const int lane = tid & 31, warp = tid >> 5;
    const int g = lane >> 2, tg = lane & 3;
    const int wm = warp >> 2, wn = warp & 3;     // wm in [0,2): rows 64*wm? no:
    // warp grid: 4 (rows) x 2 (cols)
    const int wrow = warp >> 1, wcol = warp & 1; // rows 32*wrow, cols 64*wcol
    const float* Pb = P + (size_t)bn * QLEN * QLEN;

    const int stP[2] = {0, PV_PS_FLOATS};
    const int stV[2] = {2 * PV_PS_FLOATS, 2 * PV_PS_FLOATS + PV_VS_FLOATS};

    float c[2][8][4];
    #pragma unroll
    for (int mi = 0; mi < 2; mi++)
        #pragma unroll
        for (int ni = 0; ni < 8; ni++)
            #pragma unroll
            for (int q = 0; q < 4; q++) c[mi][ni][q] = 0.f;

    const int NS = i0 / 32 + 4;   // kmax = i0 + 128

    auto load_slab = [&](int s, int st) {
        const int k0 = s * 32;
        #pragma unroll
        for (int u = 0; u < 4; u++) {
            int e = tid + u * 256;
            int m = e >> 3, kg = (e & 7) * 4;
            cp_async16(sbase + (uint32_t)(stP[st] + m * PV_PS_ROW + kg) * 4u,
                       Pb + (size_t)(i0 + m) * QLEN + k0 + kg);
        }
        #pragma unroll
        for (int u = 0; u < 4; u++) {
            int e = tid + u * 256;
            int kk = e >> 5, cc = (e & 31) * 4;
            size_t voff = (size_t)((k0 + kk) * 4 + b) * HDIM + 2048 + n * 64;
            const float* src = (cc < 64) ? (hr + voff + cc) : (hp + voff + (cc - 64));
            cp_async16(sbase + (uint32_t)(stV[st] + kk * PV_VS_ROW + cc) * 4u, src);
        }
        asm volatile("cp.async.commit_group;\n");
    };

    load_slab(0, 0);
    for (int s = 0; s < NS; s++) {
        const int st = s & 1;
        if (s + 1 < NS) { load_slab(s + 1, st ^ 1); asm volatile("cp.async.wait_group 1;\n"); }
        else            { asm volatile("cp.async.wait_group 0;\n"); }
        __syncthreads();

        const float* Ps = sm + stP[st];
        const float* Vs = sm + stV[st];
        #pragma unroll
        for (int kk = 0; kk < 4; kk++) {
            uint32_t a[2][4], bfr[8][2];
            #pragma unroll
            for (int mi = 0; mi < 2; mi++) {
                int rbase = (32 * wrow + 16 * mi + g) * PV_PS_ROW + kk * 8 + tg;
                a[mi][0] = __float_as_uint(Ps[rbase]);
                a[mi][1] = __float_as_uint(Ps[rbase + 8 * PV_PS_ROW]);
                a[mi][2] = __float_as_uint(Ps[rbase + 4]);
                a[mi][3] = __float_as_uint(Ps[rbase + 8 * PV_PS_ROW + 4]);
            }
            #pragma unroll
            for (int ni = 0; ni < 8; ni++) {
                int cidx = 64 * wcol + 8 * ni + g;
                bfr[ni][0] = __float_as_uint(Vs[(kk * 8 + tg) * PV_VS_ROW + cidx]);
                bfr[ni][1] = __float_as_uint(Vs[(kk * 8 + tg + 4) * PV_VS_ROW + cidx]);
            }
            #pragma unroll
            for (int mi = 0; mi < 2; mi++)
                #pragma unroll
                for (int ni = 0; ni < 8; ni++)
                    mma_tf32(c[mi][ni][0], c[mi][ni][1], c[mi][ni][2], c[mi][ni][3],
                             a[mi][0], a[mi][1], a[mi][2], a[mi][3],
                             bfr[ni][0], bfr[ni][1]);
        }
        __syncthreads();
    }

    float* dst = (wcol == 0) ? vr : vp;
    #pragma unroll
    for (int mi = 0; mi < 2; mi++) {
        int r0 = i0 + 32 * wrow + 16 * mi + g;
        #pragma unroll
        for (int ni = 0; ni < 8; ni++) {
            int ch = 8 * ni + 2 * tg;   // within the 64-wide half
            size_t o0 = (size_t)(r0 * 4 + b) * EDIM + n * 64 + ch;
            size_t o1 = (size_t)((r0 + 8) * 4 + b) * EDIM + n * 64 + ch;
            *(float2*)&dst[o0] = make_float2(c[mi][ni][0], c[mi][ni][1]);
            *(float2*)&dst[o1] = make_float2(c[mi][ni][2], c[mi][ni][3]);
        }
    }
}

// ---------------- LayerNorm over E ----------------------------------------
__global__ void __launch_bounds__(256) ln_kernel(
    const float* __restrict__ Y, const float* __restrict__ g,
    const float* __restrict__ be, float* __restrict__ out)
{
    const int row = blockIdx.x;
    const float* y = Y + (size_t)row * EDIM;
    float* o = out + (size_t)row * EDIM;
    const int tid = threadIdx.x;
    __shared__ float red[256];

    float s = 0.f;
    for (int e = tid; e < EDIM; e += 256) s += y[e];
    red[tid] = s; __syncthreads();
    for (int k = 128; k > 0; k >>= 1) { if (tid < k) red[tid] += red[tid + k]; __syncthreads(); }
    const float mu = red[0] * (1.f / EDIM);
    __syncthreads();

    float sq = 0.f;
    for (int e = tid; e < EDIM; e += 256) { float d = y[e] - mu; sq += d * d; }
    red[tid] = sq; __syncthreads();
    for (int k = 128; k > 0; k >>= 1) { if (tid < k) red[tid] += red[tid + k]; __syncthreads(); }
    const float rstd = rsqrtf(red[0] * (1.f / EDIM) + LN_EPS);

    for (int e = tid; e < EDIM; e += 256)
        o[e] = (y[e] - mu) * rstd * g[e] + be[e];
}

// ---------------- launch ---------------------------------------------------
extern "C" void kernel_launch(void* const* d_in, const int* in_sizes, int n_in,
                              void* d_out, int out_size)
{
    (void)in_sizes; (void)n_in; (void)out_size;
    const float* w_real  = (const float*)d_in[0];
    const float* w_phase = (const float*)d_in[1];
    const float* r       = (const float*)d_in[2];
    const float* r_w_b   = (const float*)d_in[3];
    const float* r_r_b   = (const float*)d_in[4];
    const float* W_qkv   = (const float*)d_in[5];
    const float* W_qkv1  = (const float*)d_in[6];
    const float* W_r     = (const float*)d_in[7];
    const float* W_o     = (const float*)d_in[8];
    const float* W_o1    = (const float*)d_in[9];
    const float* gamma   = (const float*)d_in[10];
    const float* beta    = (const float*)d_in[11];

    float *heads_r, *heads_p, *rkb, *S, *vecr, *vecp, *yr, *yp;
    cudaGetSymbolAddress((void**)&heads_r, g_heads_r);
    cudaGetSymbolAddress((void**)&heads_p, g_heads_p);
    cudaGetSymbolAddress((void**)&rkb,     g_rk);
    cudaGetSymbolAddress((void**)&S,       g_S);
    cudaGetSymbolAddress((void**)&vecr,    g_vecr);
    cudaGetSymbolAddress((void**)&vecp,    g_vecp);
    cudaGetSymbolAddress((void**)&yr,      g_yr);
    cudaGetSymbolAddress((void**)&yp,      g_yp);

    cudaFuncSetAttribute(tf32_gemm_tn, cudaFuncAttributeMaxDynamicSharedMemorySize, GEMM_SMEM_BYTES);
    cudaFuncSetAttribute(score_kernel, cudaFuncAttributeMaxDynamicSharedMemorySize, SK_SMEM_BYTES);
    cudaFuncSetAttribute(pv_kernel,    cudaFuncAttributeMaxDynamicSharedMemorySize, PV_SMEM_BYTES);

    // projections (tensor cores, tf32)
    tf32_gemm_tn<<<dim3(HDIM / 128, MB / 128), 128, GEMM_SMEM_BYTES>>>(w_real,  W_qkv,  nullptr, heads_r, MB, HDIM, EDIM);
    tf32_gemm_tn<<<dim3(HDIM / 128, MB / 128), 128, GEMM_SMEM_BYTES>>>(w_phase, W_qkv1, nullptr, heads_p, MB, HDIM, EDIM);
    tf32_gemm_tn<<<dim3(8, 8), 128, GEMM_SMEM_BYTES>>>(r, W_r, nullptr, rkb, QLEN, NH * DH, EDIM);

    // fused scores (lower-triangular tiles only, tensor cores)
    score_kernel<<<dim3(136, 64), 256, SK_SMEM_BYTES>>>(heads_r, heads_p, rkb, r_w_b, r_r_b, S);

    softmax_kernel<<<dim3(QLEN, 64), 256>>>(S);
    pv_kernel<<<dim3(QLEN / 128, 64), 256, PV_SMEM_BYTES>>>(S, heads_r, heads_p, vecr, vecp);

    // output projections with residual (tensor cores), then LN
    tf32_gemm_tn<<<dim3(EDIM / 128, MB / 128), 128, GEMM_SMEM_BYTES>>>(vecr, W_o,  w_real,  yr, MB, EDIM, EDIM);
    tf32_gemm_tn<<<dim3(EDIM / 128, MB / 128), 128, GEMM_SMEM_BYTES>>>(vecp, W_o1, w_phase, yp, MB, EDIM, EDIM);

    float* out = (float*)d_out;
    ln_kernel<<<MB, 256>>>(yr, gamma, beta, out);
    ln_kernel<<<MB, 256>>>(yp, gamma, beta, out + (size_t)MB * EDIM);
}

// round 4
// speedup vs baseline: 4.3211x; 1.2073x over previous
#include <cuda_runtime.h>
#include <math.h>
#include <stdint.h>

#define QLEN 1024
#define BSZ  4
#define EDIM 1024
#define NH   16
#define DH   64
#define SCALE_F 0.125f
#define LN_EPS 1e-5f

#define MB (QLEN * BSZ)
#define HDIM (3 * NH * DH)        // 3072

// ---------------- scratch (device globals: allocation-free) ----------------
__device__ float g_heads_r[(size_t)MB * HDIM];
__device__ float g_heads_p[(size_t)MB * HDIM];
__device__ float g_rk[(size_t)QLEN * NH * DH];
__device__ float g_vecr[(size_t)MB * EDIM];
__device__ float g_vecp[(size_t)MB * EDIM];
__device__ float g_yr[(size_t)MB * EDIM];
__device__ float g_yp[(size_t)MB * EDIM];

__device__ __forceinline__ void cp_async16(uint32_t dst, const void* src) {
    asm volatile("cp.async.ca.shared.global [%0], [%1], 16;\n" :: "r"(dst), "l"(src));
}
__device__ __forceinline__ void mma_tf32(
    float& c0, float& c1, float& c2, float& c3,
    uint32_t a0, uint32_t a1, uint32_t a2, uint32_t a3,
    uint32_t b0, uint32_t b1)
{
    asm volatile(
        "mma.sync.aligned.m16n8k8.row.col.f32.tf32.tf32.f32 "
        "{%0,%1,%2,%3}, {%4,%5,%6,%7}, {%8,%9}, {%0,%1,%2,%3};\n"
        : "+f"(c0), "+f"(c1), "+f"(c2), "+f"(c3)
        : "r"(a0), "r"(a1), "r"(a2), "r"(a3), "r"(b0), "r"(b1));
}

// ================= TF32 tensor-core GEMM: C(M,N) = A(M,K) @ B(N,K)^T [+R] ==
#define SLAB_ROW 36
#define SLAB_FLOATS (128 * SLAB_ROW)
#define GEMM_SMEM_BYTES (4 * SLAB_FLOATS * 4)

__global__ void __launch_bounds__(128) tf32_gemm_tn(
    const float* __restrict__ A, const float* __restrict__ B,
    const float* __restrict__ R, float* __restrict__ C,
    int M, int N, int K)
{
    extern __shared__ float sm[];
    const uint32_t sbase = (uint32_t)__cvta_generic_to_shared(sm);
    const int tid = threadIdx.x;
    const int lane = tid & 31, warp = tid >> 5;
    const int g = lane >> 2, tg = lane & 3;
    const int wm = warp >> 1, wn = warp & 1;
    const int m0 = blockIdx.y * 128, n0 = blockIdx.x * 128;

    const int stA[2] = {0, 2 * SLAB_FLOATS};
    const int stB[2] = {SLAB_FLOATS, 3 * SLAB_FLOATS};

    float c[4][8][4];
    #pragma unroll
    for (int mi = 0; mi < 4; mi++)
        #pragma unroll
        for (int ni = 0; ni < 8; ni++)
            #pragma unroll
            for (int q = 0; q < 4; q++) c[mi][ni][q] = 0.f;

    const int NS = K / 32;
    auto load_slab = [&](int s, int st) {
        const int k0 = s * 32;
        #pragma unroll
        for (int u = 0; u < 8; u++) {
            int e = tid + u * 128;
            int m = e >> 3, kg = e & 7;
            cp_async16(sbase + (uint32_t)(stA[st] + m * SLAB_ROW + kg * 4) * 4u,
                       A + (size_t)(m0 + m) * K + k0 + kg * 4);
            cp_async16(sbase + (uint32_t)(stB[st] + m * SLAB_ROW + kg * 4) * 4u,
                       B + (size_t)(n0 + m) * K + k0 + kg * 4);
        }
        asm volatile("cp.async.commit_group;\n");
    };

    load_slab(0, 0);
    for (int s = 0; s < NS; s++) {
        const int st = s & 1;
        if (s + 1 < NS) { load_slab(s + 1, st ^ 1); asm volatile("cp.async.wait_group 1;\n"); }
        else            { asm volatile("cp.async.wait_group 0;\n"); }
        __syncthreads();

        const float* As = sm + stA[st];
        const float* Bs = sm + stB[st];
        #pragma unroll
        for (int kk = 0; kk < 4; kk++) {
            uint32_t a[4][4], b[8][2];
            #pragma unroll
            for (int mi = 0; mi < 4; mi++) {
                int base = (wm * 64 + mi * 16 + g) * SLAB_ROW + kk * 8 + tg;
                a[mi][0] = __float_as_uint(As[base]);
                a[mi][1] = __float_as_uint(As[base + 8 * SLAB_ROW]);
                a[mi][2] = __float_as_uint(As[base + 4]);
                a[mi][3] = __float_as_uint(As[base + 8 * SLAB_ROW + 4]);
            }
            #pragma unroll
            for (int ni = 0; ni < 8; ni++) {
                int base = (wn * 64 + ni * 8 + g) * SLAB_ROW + kk * 8 + tg;
                b[ni][0] = __float_as_uint(Bs[base]);
                b[ni][1] = __float_as_uint(Bs[base + 4]);
            }
            #pragma unroll
            for (int mi = 0; mi < 4; mi++)
                #pragma unroll
                for (int ni = 0; ni < 8; ni++)
                    mma_tf32(c[mi][ni][0], c[mi][ni][1], c[mi][ni][2], c[mi][ni][3],
                             a[mi][0], a[mi][1], a[mi][2], a[mi][3],
                             b[ni][0], b[ni][1]);
        }
        __syncthreads();
    }

    #pragma unroll
    for (int mi = 0; mi < 4; mi++) {
        int r0 = m0 + wm * 64 + mi * 16 + g;
        #pragma unroll
        for (int ni = 0; ni < 8; ni++) {
            int cc = n0 + wn * 64 + ni * 8 + 2 * tg;
            float2 v0 = make_float2(c[mi][ni][0], c[mi][ni][1]);
            float2 v1 = make_float2(c[mi][ni][2], c[mi][ni][3]);
            if (R) {
                float2 u0 = *(const float2*)&R[(size_t)r0 * N + cc];
                float2 u1 = *(const float2*)&R[(size_t)(r0 + 8) * N + cc];
                v0.x += u0.x; v0.y += u0.y; v1.x += u1.x; v1.y += u1.y;
            }
            *(float2*)&C[(size_t)r0 * N + cc] = v0;
            *(float2*)&C[(size_t)(r0 + 8) * N + cc] = v1;
        }
    }
}

// ================= fused attention: scores + online softmax + PV ===========
// One CTA per (bn, 64-row q block). Loops over causal j tiles (jt = 0..it).
// smem layout (floats):
#define FK_QR   0
#define FK_QP   (64 * 68)                        // 4352
#define FK_KR   (2 * 64 * 68)                    // 8704
#define FK_KP   (3 * 64 * 68)                    // 13056
#define FK_RK   (4 * 64 * 68)                    // 17408, size 128*68
#define FK_KEND (4 * 64 * 68 + 128 * 68)         // 26112
#define FK_ER   FK_KR                            // 64*132 = 8448, aliases kr/kp/rk
#define FK_EP   (FK_KR + 8448)                   // ends 25600 < 26112
#define FK_V    FK_KEND                          // 64*136 = 8704
#define FK_P    (FK_KEND + 64 * 136)             // 34816, size 64*68
#define FK_WKR  (FK_P + 64 * 68)                 // 39168
#define FK_WKP  (FK_WKR + 64)
#define FK_BRK  (FK_WKR + 128)                   // 128 entries
#define FK_RWB  (FK_WKR + 256)
#define FK_RRB  (FK_WKR + 320)
#define FK_MRUN (FK_WKR + 384)                   // 64
#define FK_LRUN (FK_MRUN + 64)                   // 64
#define FK_MT   (FK_LRUN + 64)                   // mtmp[2][64]
#define FK_LT   (FK_MT + 128)                    // ltmp[2][64]
#define FK_FLOATS (FK_LT + 128)
#define FK_SMEM_BYTES (FK_FLOATS * 4)            // ~158 KB

__global__ void __launch_bounds__(256) attn_fused_kernel(
    const float* __restrict__ hr, const float* __restrict__ hp,
    const float* __restrict__ rk, const float* __restrict__ rwb,
    const float* __restrict__ rrb,
    float* __restrict__ vecr, float* __restrict__ vecp)
{
    extern __shared__ float sm[];
    const uint32_t sbase = (uint32_t)__cvta_generic_to_shared(sm);
    const int it = blockIdx.x;
    const int bn = blockIdx.y;
    const int b = bn >> 4, n = bn & 15;
    const int i0 = it * 64;
    const int tid = threadIdx.x;
    const int lane = tid & 31, warp = tid >> 5;
    const int g = lane >> 2, tg = lane & 3;
    const int wm = warp >> 1, wn = warp & 1;
    const int rloc0 = 16 * wm + g;               // base local row for this thread

    // ---- persistent loads: q tiles, biases, stats init ----
    #pragma unroll
    for (int u = 0; u < 4; u++) {
        int e = tid + u * 256;
        int row = e >> 4, f4 = (e & 15) * 4;
        size_t qoff = (size_t)((i0 + row) * 4 + b) * HDIM + n * 64 + f4;
        *(float4*)&sm[FK_QR + row * 68 + f4] = *(const float4*)&hr[qoff];
        *(float4*)&sm[FK_QP + row * 68 + f4] = *(const float4*)&hp[qoff];
    }
    if (tid < 64)        sm[FK_RWB + tid] = rwb[n * 64 + tid];
    else if (tid < 128)  sm[FK_RRB + (tid - 64)] = rrb[n * 64 + (tid - 64)];
    else if (tid < 192)  { sm[FK_MRUN + (tid - 128)] = -1e30f; sm[FK_LRUN + (tid - 128)] = 0.f; }

    // O accumulators: rows {rloc0, rloc0+8}, cols 64*wn + 8*ni + 2*tg + {0,1}
    float O[8][4];
    #pragma unroll
    for (int ni = 0; ni < 8; ni++)
        #pragma unroll
        for (int q = 0; q < 4; q++) O[ni][q] = 0.f;

    for (int jt = 0; jt <= it; jt++) {
        const int j0 = jt * 64;
        const int base = 960 + j0 - i0;
        const bool diag = (jt == it);

        __syncthreads();   // previous iteration's consumers done before refill

        // ---- async loads: kr, kp, rk window, V ----
        #pragma unroll
        for (int u = 0; u < 4; u++) {
            int e = tid + u * 256;
            int row = e >> 4, f4 = (e & 15) * 4;
            size_t koff = (size_t)((j0 + row) * 4 + b) * HDIM + 1024 + n * 64 + f4;
            cp_async16(sbase + (uint32_t)(FK_KR + row * 68 + f4) * 4u, hr + koff);
            cp_async16(sbase + (uint32_t)(FK_KP + row * 68 + f4) * 4u, hp + koff);
        }
        #pragma unroll
        for (int u = 0; u < 8; u++) {
            int e = tid + u * 256;
            int row = e >> 4, f4 = (e & 15) * 4;
            int krow = base + row; krow = krow > 1023 ? 1023 : krow;
            cp_async16(sbase + (uint32_t)(FK_RK + row * 68 + f4) * 4u,
                       rk + (size_t)krow * (NH * DH) + n * 64 + f4);
        }
        #pragma unroll
        for (int u = 0; u < 8; u++) {
            int e = tid + u * 256;
            int row = e >> 5, cc = (e & 31) * 4;
            size_t voff = (size_t)((j0 + row) * 4 + b) * HDIM + 2048 + n * 64;
            const float* src = (cc < 64) ? (hr + voff + cc) : (hp + voff + (cc - 64));
            cp_async16(sbase + (uint32_t)(FK_V + row * 136 + cc) * 4u, src);
        }
        asm volatile("cp.async.commit_group;\n");
        asm volatile("cp.async.wait_group 0;\n");
        __syncthreads();

        // ---- per-column bias vectors ----
        if (tid < 64) {
            float s = 0.f;
            #pragma unroll 8
            for (int d = 0; d < 64; d++) s += sm[FK_RWB + d] * sm[FK_KR + tid * 68 + d];
            sm[FK_WKR + tid] = s;
        } else if (tid < 128) {
            int j = tid - 64; float s = 0.f;
            #pragma unroll 8
            for (int d = 0; d < 64; d++) s += sm[FK_RWB + d] * sm[FK_KP + j * 68 + d];
            sm[FK_WKP + j] = s;
        } else {
            int L = tid - 128; float s = 0.f;
            #pragma unroll 8
            for (int d = 0; d < 64; d++) s += sm[FK_RRB + d] * sm[FK_RK + L * 68 + d];
            sm[FK_BRK + L] = s;
        }
        __syncthreads();

        // ---- mma pass: 5 products (identical layout to R3 score kernel) ----
        float A1[4][4] = {}, A2[4][4] = {}, A3[4][4] = {};
        float B1[8][4] = {}, B2[8][4] = {};

        #pragma unroll
        for (int kk = 0; kk < 8; kk++) {
            int arow = rloc0 * 68 + kk * 8 + tg;
            uint32_t aqr0 = __float_as_uint(sm[FK_QR + arow]);
            uint32_t aqr1 = __float_as_uint(sm[FK_QR + arow + 8 * 68]);
            uint32_t aqr2 = __float_as_uint(sm[FK_QR + arow + 4]);
            uint32_t aqr3 = __float_as_uint(sm[FK_QR + arow + 8 * 68 + 4]);
            uint32_t aqp0 = __float_as_uint(sm[FK_QP + arow]);
            uint32_t aqp1 = __float_as_uint(sm[FK_QP + arow + 8 * 68]);
            uint32_t aqp2 = __float_as_uint(sm[FK_QP + arow + 4]);
            uint32_t aqp3 = __float_as_uint(sm[FK_QP + arow + 8 * 68 + 4]);

            #pragma unroll
            for (int ni = 0; ni < 4; ni++) {
                int brow = (32 * wn + 8 * ni + g) * 68 + kk * 8 + tg;
                uint32_t bkr0 = __float_as_uint(sm[FK_KR + brow]);
                uint32_t bkr1 = __float_as_uint(sm[FK_KR + brow + 4]);
                uint32_t bkp0 = __float_as_uint(sm[FK_KP + brow]);
                uint32_t bkp1 = __float_as_uint(sm[FK_KP + brow + 4]);
                mma_tf32(A1[ni][0], A1[ni][1], A1[ni][2], A1[ni][3],
                         aqr0, aqr1, aqr2, aqr3, bkr0, bkr1);
                mma_tf32(A2[ni][0], A2[ni][1], A2[ni][2], A2[ni][3],
                         aqp0, aqp1, aqp2, aqp3, bkp0, bkp1);
                mma_tf32(A3[ni][0], A3[ni][1], A3[ni][2], A3[ni][3],
                         aqr0, aqr1, aqr2, aqr3, bkp0, bkp1);
            }
            #pragma unroll
            for (int li = 0; li < 8; li++) {
                int rrow = (64 * wn + 8 * li + g) * 68 + kk * 8 + tg;
                uint32_t br0 = __float_as_uint(sm[FK_RK + rrow]);
                uint32_t br1 = __float_as_uint(sm[FK_RK + rrow + 4]);
                mma_tf32(B1[li][0], B1[li][1], B1[li][2], B1[li][3],
                         aqr0, aqr1, aqr2, aqr3, br0, br1);
                mma_tf32(B2[li][0], B2[li][1], B2[li][2], B2[li][3],
                         aqp0, aqp1, aqp2, aqp3, br0, br1);
            }
        }

        // ---- stage E through smem (aliases kr/kp/rk) ----
        __syncthreads();
        #pragma unroll
        for (int li = 0; li < 8; li++) {
            #pragma unroll
            for (int q = 0; q < 4; q++) {
                int row = rloc0 + 8 * (q >> 1);
                int col = 64 * wn + 8 * li + 2 * tg + (q & 1);
                sm[FK_ER + row * 132 + col] = B1[li][q];
                sm[FK_EP + row * 132 + col] = B2[li][q];
            }
        }
        __syncthreads();

        // ---- combine into scores (registers) ----
        float sv[4][4];
        #pragma unroll
        for (int ni = 0; ni < 4; ni++) {
            #pragma unroll
            for (int q = 0; q < 4; q++) {
                int row = rloc0 + 8 * (q >> 1);
                int col = 32 * wn + 8 * ni + 2 * tg + (q & 1);
                float wkp_c = sm[FK_WKP + col];
                float acr = A1[ni][q] + sm[FK_WKR + col] - A2[ni][q] - wkp_c;
                float acp = 2.0f * (A3[ni][q] + wkp_c);
                int L = col - row + 63;
                float bb = sm[FK_BRK + L];
                float b1v = sm[FK_ER + row * 132 + L] + bb;
                float b2v = sm[FK_EP + row * 132 + L] + bb;
                float s = (sqrtf(acr * acr + acp * acp) + sqrtf(b1v * b1v + b2v * b2v)) * SCALE_F;
                if (diag && col > row) s = -1e30f;
                sv[ni][q] = s;
            }
        }

        // ---- online softmax: row max ----
        float pm[2] = {-1e30f, -1e30f};
        #pragma unroll
        for (int ni = 0; ni < 4; ni++) {
            #pragma unroll
            for (int q = 0; q < 4; q++) pm[q >> 1] = fmaxf(pm[q >> 1], sv[ni][q]);
        }
        #pragma unroll
        for (int rh = 0; rh < 2; rh++) {
            pm[rh] = fmaxf(pm[rh], __shfl_xor_sync(0xffffffffu, pm[rh], 1));
            pm[rh] = fmaxf(pm[rh], __shfl_xor_sync(0xffffffffu, pm[rh], 2));
        }
        sm[FK_MT + wn * 64 + rloc0]     = pm[0];
        sm[FK_MT + wn * 64 + rloc0 + 8] = pm[1];
        __syncthreads();

        float mold[2], mnew[2], alpha[2], psum[2] = {0.f, 0.f};
        #pragma unroll
        for (int rh = 0; rh < 2; rh++) {
            int r = rloc0 + 8 * rh;
            mold[rh] = sm[FK_MRUN + r];
            mnew[rh] = fmaxf(mold[rh], fmaxf(sm[FK_MT + r], sm[FK_MT + 64 + r]));
            alpha[rh] = __expf(mold[rh] - mnew[rh]);
        }
        #pragma unroll
        for (int ni = 0; ni < 4; ni++) {
            #pragma unroll
            for (int q = 0; q < 4; q++) {
                int rh = q >> 1;
                int row = rloc0 + 8 * rh;
                int col = 32 * wn + 8 * ni + 2 * tg + (q & 1);
                float p = __expf(sv[ni][q] - mnew[rh]);
                psum[rh] += p;
                sm[FK_P + row * 68 + col] = p;
            }
        }
        #pragma unroll
        for (int rh = 0; rh < 2; rh++) {
            psum[rh] += __shfl_xor_sync(0xffffffffu, psum[rh], 1);
            psum[rh] += __shfl_xor_sync(0xffffffffu, psum[rh], 2);
        }
        sm[FK_LT + wn * 64 + rloc0]     = psum[0];
        sm[FK_LT + wn * 64 + rloc0 + 8] = psum[1];
        // rescale O
        #pragma unroll
        for (int ni = 0; ni < 8; ni++) {
            #pragma unroll
            for (int q = 0; q < 4; q++) O[ni][q] *= alpha[q >> 1];
        }
        __syncthreads();

        if (wn == 0 && tg == 0) {
            #pragma unroll
            for (int rh = 0; rh < 2; rh++) {
                int r = rloc0 + 8 * rh;
                sm[FK_MRUN + r] = mnew[rh];
                sm[FK_LRUN + r] = sm[FK_LRUN + r] * alpha[rh]
                                  + sm[FK_LT + r] + sm[FK_LT + 64 + r];
            }
        }

        // ---- PV mma: O += P(64x64) @ V(64x128) ----
        #pragma unroll
        for (int kk = 0; kk < 8; kk++) {
            int arow = rloc0 * 68 + kk * 8 + tg;
            uint32_t a0 = __float_as_uint(sm[FK_P + arow]);
            uint32_t a1 = __float_as_uint(sm[FK_P + arow + 8 * 68]);
            uint32_t a2 = __float_as_uint(sm[FK_P + arow + 4]);
            uint32_t a3 = __float_as_uint(sm[FK_P + arow + 8 * 68 + 4]);
            #pragma unroll
            for (int ni = 0; ni < 8; ni++) {
                int ch = 64 * wn + 8 * ni + g;
                uint32_t b0 = __float_as_uint(sm[FK_V + (kk * 8 + tg) * 136 + ch]);
                uint32_t b1 = __float_as_uint(sm[FK_V + (kk * 8 + tg + 4) * 136 + ch]);
                mma_tf32(O[ni][0], O[ni][1], O[ni][2], O[ni][3],
                         a0, a1, a2, a3, b0, b1);
            }
        }
    }

    __syncthreads();
    float linv[2] = {1.f / sm[FK_LRUN + rloc0], 1.f / sm[FK_LRUN + rloc0 + 8]};
    float* dst = (wn == 0) ? vecr : vecp;
    #pragma unroll
    for (int ni = 0; ni < 8; ni++) {
        int ch = 8 * ni + 2 * tg;
        int r0 = i0 + rloc0;
        size_t o0 = (size_t)(r0 * 4 + b) * EDIM + n * 64 + ch;
        size_t o1 = (size_t)((r0 + 8) * 4 + b) * EDIM + n * 64 + ch;
        *(float2*)&dst[o0] = make_float2(O[ni][0] * linv[0], O[ni][1] * linv[0]);
        *(float2*)&dst[o1] = make_float2(O[ni][2] * linv[1], O[ni][3] * linv[1]);
    }
}

// ---------------- LayerNorm over E ----------------------------------------
__global__ void __launch_bounds__(256) ln_kernel(
    const float* __restrict__ Y, const float* __restrict__ g,
    const float* __restrict__ be, float* __restrict__ out)
{
    const int row = blockIdx.x;
    const float* y = Y + (size_t)row * EDIM;
    float* o = out + (size_t)row * EDIM;
    const int tid = threadIdx.x;
    __shared__ float red[256];

    float s = 0.f;
    for (int e = tid; e < EDIM; e += 256) s += y[e];
    red[tid] = s; __syncthreads();
    for (int k = 128; k > 0; k >>= 1) { if (tid < k) red[tid] += red[tid + k]; __syncthreads(); }
    const float mu = red[0] * (1.f / EDIM);
    __syncthreads();

    float sq = 0.f;
    for (int e = tid; e < EDIM; e += 256) { float d = y[e] - mu; sq += d * d; }
    red[tid] = sq; __syncthreads();
    for (int k = 128; k > 0; k >>= 1) { if (tid < k) red[tid] += red[tid + k]; __syncthreads(); }
    const float rstd = rsqrtf(red[0] * (1.f / EDIM) + LN_EPS);

    for (int e = tid; e < EDIM; e += 256)
        o[e] = (y[e] - mu) * rstd * g[e] + be[e];
}

// ---------------- launch ---------------------------------------------------
extern "C" void kernel_launch(void* const* d_in, const int* in_sizes, int n_in,
                              void* d_out, int out_size)
{
    (void)in_sizes; (void)n_in; (void)out_size;
    const float* w_real  = (const float*)d_in[0];
    const float* w_phase = (const float*)d_in[1];
    const float* r       = (const float*)d_in[2];
    const float* r_w_b   = (const float*)d_in[3];
    const float* r_r_b   = (const float*)d_in[4];
    const float* W_qkv   = (const float*)d_in[5];
    const float* W_qkv1  = (const float*)d_in[6];
    const float* W_r     = (const float*)d_in[7];
    const float* W_o     = (const float*)d_in[8];
    const float* W_o1    = (const float*)d_in[9];
    const float* gamma   = (const float*)d_in[10];
    const float* beta    = (const float*)d_in[11];

    float *heads_r, *heads_p, *rkb, *vecr, *vecp, *yr, *yp;
    cudaGetSymbolAddress((void**)&heads_r, g_heads_r);
    cudaGetSymbolAddress((void**)&heads_p, g_heads_p);
    cudaGetSymbolAddress((void**)&rkb,     g_rk);
    cudaGetSymbolAddress((void**)&vecr,    g_vecr);
    cudaGetSymbolAddress((void**)&vecp,    g_vecp);
    cudaGetSymbolAddress((void**)&yr,      g_yr);
    cudaGetSymbolAddress((void**)&yp,      g_yp);

    cudaFuncSetAttribute(tf32_gemm_tn, cudaFuncAttributeMaxDynamicSharedMemorySize, GEMM_SMEM_BYTES);
    cudaFuncSetAttribute(attn_fused_kernel, cudaFuncAttributeMaxDynamicSharedMemorySize, FK_SMEM_BYTES);

    // projections (tensor cores, tf32)
    tf32_gemm_tn<<<dim3(HDIM / 128, MB / 128), 128, GEMM_SMEM_BYTES>>>(w_real,  W_qkv,  nullptr, heads_r, MB, HDIM, EDIM);
    tf32_gemm_tn<<<dim3(HDIM / 128, MB / 128), 128, GEMM_SMEM_BYTES>>>(w_phase, W_qkv1, nullptr, heads_p, MB, HDIM, EDIM);
    tf32_gemm_tn<<<dim3(8, 8), 128, GEMM_SMEM_BYTES>>>(r, W_r, nullptr, rkb, QLEN, NH * DH, EDIM);

    // fused attention: scores + softmax + PV
    attn_fused_kernel<<<dim3(16, 64), 256, FK_SMEM_BYTES>>>(
        heads_r, heads_p, rkb, r_w_b, r_r_b, vecr, vecp);

    // output projections with residual (tensor cores), then LN
    tf32_gemm_tn<<<dim3(EDIM / 128, MB / 128), 128, GEMM_SMEM_BYTES>>>(vecr, W_o,  w_real,  yr, MB, EDIM, EDIM);
    tf32_gemm_tn<<<dim3(EDIM / 128, MB / 128), 128, GEMM_SMEM_BYTES>>>(vecp, W_o1, w_phase, yp, MB, EDIM, EDIM);

    float* out = (float*)d_out;
    ln_kernel<<<MB, 256>>>(yr, gamma, beta, out);
    ln_kernel<<<MB, 256>>>(yp, gamma, beta, out + (size_t)MB * EDIM);
}